// round 9
// baseline (speedup 1.0000x reference)
#include <cuda_runtime.h>
#include <math.h>
#include <stdint.h>

#define NL   4
#define NB   4
#define SEQ  2048
#define DM   256
#define NH   8
#define DH   32
#define DF   512
#define MR   (NB*SEQ)

#define NEGF (-3.402823466e38f)
#define L2E  1.44269504088896340736f

typedef unsigned long long u64;

// ================= bf16 helpers =================
__device__ __forceinline__ uint32_t pack_bf16x2(float lo, float hi) {
    uint32_t r; asm("cvt.rn.bf16x2.f32 %0, %1, %2;" : "=r"(r) : "f"(hi), "f"(lo)); return r;
}
__device__ __forceinline__ float bf_low(uint32_t p)  { return __uint_as_float(p << 16); }
__device__ __forceinline__ float bf_high(uint32_t p) { return __uint_as_float(p & 0xffff0000u); }
__device__ __forceinline__ float ex2f(float x) {
    float r; asm("ex2.approx.f32 %0, %1;" : "=f"(r) : "f"(x)); return r;
}

__device__ __forceinline__ void mma_bf16(float* c, const uint32_t* a, const uint32_t* b) {
    asm volatile(
        "mma.sync.aligned.m16n8k16.row.col.f32.bf16.bf16.f32 "
        "{%0,%1,%2,%3},{%4,%5,%6,%7},{%8,%9},{%0,%1,%2,%3};"
        : "+f"(c[0]), "+f"(c[1]), "+f"(c[2]), "+f"(c[3])
        : "r"(a[0]), "r"(a[1]), "r"(a[2]), "r"(a[3]), "r"(b[0]), "r"(b[1]));
}

// ================= scratch =================
__device__ float g_qkv [3*(size_t)MR*DM];
__device__ float g_xc  [(size_t)MR*DM];

// packed activation planes [row][kpair]
__device__ uint32_t g_pxc_h[(size_t)MR*128];
__device__ uint32_t g_pxc_l[(size_t)MR*128];
__device__ uint32_t g_pff_h[(size_t)MR*256];
__device__ uint32_t g_pff_l[(size_t)MR*256];
__device__ uint32_t g_po_h [(size_t)MR*128];
__device__ uint32_t g_po_l [(size_t)MR*128];

// packed K: [bh][dim-pair 16][key 2048] hi/lo;  packed V: [bh][dim 32][key-pair 1024] hi/lo
__device__ uint32_t g_kph[NB*NH*16*SEQ];
__device__ uint32_t g_kpl[NB*NH*16*SEQ];
__device__ uint32_t g_vph[NB*NH*32*(SEQ/2)];
__device__ uint32_t g_vpl[NB*NH*32*(SEQ/2)];
__device__ unsigned g_kmax2[NB*NH];

// packed bf16 hi/lo weights
__device__ uint32_t g_pwqkv_h[NL*3*DM*(DM/2)];
__device__ uint32_t g_pwqkv_l[NL*3*DM*(DM/2)];
__device__ uint32_t g_pwo_h  [NL*DM*(DM/2)];
__device__ uint32_t g_pwo_l  [NL*DM*(DM/2)];
__device__ uint32_t g_pw1_h  [NL*DF*(DM/2)];
__device__ uint32_t g_pw1_l  [NL*DF*(DM/2)];
__device__ uint32_t g_pw2_h  [NL*DM*(DF/2)];
__device__ uint32_t g_pw2_l  [NL*DM*(DF/2)];

// ================= packing kernels =================
__global__ void pack_qkv(const float* __restrict__ Wq,
                         const float* __restrict__ Wk,
                         const float* __restrict__ Wv) {
    int i = blockIdx.x * blockDim.x + threadIdx.x;
    const int PER_M = DM * (DM/2);
    const int TOT = NL * 3 * PER_M;
    if (i >= TOT) return;
    int l  = i / (3*PER_M);
    int r  = i % (3*PER_M);
    int m  = r / PER_M;
    int r2 = r % PER_M;
    int n  = r2 >> 7;
    int kp = r2 & 127;
    int h = n >> 5, e = n & 31;
    const float* W = (m == 0) ? Wq : (m == 1) ? Wk : Wv;
    size_t s0 = (((size_t)l*NH + h)*DM + 2*kp)*DH + e;
    float v0 = W[s0], v1 = W[s0 + DH];
    uint32_t hp = pack_bf16x2(v0, v1);
    g_pwqkv_h[i] = hp;
    g_pwqkv_l[i] = pack_bf16x2(v0 - bf_low(hp), v1 - bf_high(hp));
}

__global__ void pack_w(const float* __restrict__ W, uint32_t* __restrict__ dh,
                       uint32_t* __restrict__ dl, int K, int N) {
    int i = blockIdx.x * blockDim.x + threadIdx.x;
    int per = N * (K >> 1);
    if (i >= NL * per) return;
    int l = i / per, r = i % per;
    int n = r / (K >> 1), kp = r % (K >> 1);
    size_t s = (size_t)l*K*N + (size_t)(2*kp)*N + n;
    float v0 = W[s], v1 = W[s + N];
    uint32_t hp = pack_bf16x2(v0, v1);
    dh[i] = hp;
    dl[i] = pack_bf16x2(v0 - bf_low(hp), v1 - bf_high(hp));
}

// pack fp32 row-major activations into hi/lo planes [row][kpair]
__global__ void pack_a(const float* __restrict__ A, uint32_t* __restrict__ dh,
                       uint32_t* __restrict__ dl, int total_pairs) {
    int i = blockIdx.x * blockDim.x + threadIdx.x;
    if (i >= total_pairs) return;
    float2 v = ((const float2*)A)[i];
    uint32_t hp = pack_bf16x2(v.x, v.y);
    dh[i] = hp;
    dl[i] = pack_bf16x2(v.x - bf_low(hp), v.y - bf_high(hp));
}

__global__ void reset_kmax() {
    if (threadIdx.x < NB*NH) g_kmax2[threadIdx.x] = 0u;
}

// ================= K/V transpose + split-bf16 pack (+ K norm max) ==========
__global__ void pack_kv(const float* __restrict__ k, const float* __restrict__ v) {
    __shared__ float tl[32][33];
    int bh = blockIdx.y;
    int b = bh >> 3, h = bh & 7;
    int l0 = blockIdx.x * 32;
    const float* src = (blockIdx.z == 0) ? k : v;
    #pragma unroll
    for (int kk = 0; kk < 4; kk++) {
        int l = l0 + threadIdx.y + kk*8;
        tl[threadIdx.y + kk*8][threadIdx.x] = src[((size_t)b*SEQ + l)*DM + h*32 + threadIdx.x];
    }
    __syncthreads();
    if (blockIdx.z == 0) {
        #pragma unroll
        for (int kk = 0; kk < 2; kk++) {
            int dp = threadIdx.y + kk*8;
            float v0 = tl[threadIdx.x][2*dp], v1 = tl[threadIdx.x][2*dp+1];
            uint32_t hp = pack_bf16x2(v0, v1);
            size_t o = ((size_t)bh*16 + dp)*SEQ + l0 + threadIdx.x;
            g_kph[o] = hp;
            g_kpl[o] = pack_bf16x2(v0 - bf_low(hp), v1 - bf_high(hp));
        }
        if (threadIdx.y == 0) {
            float n2 = 0.f;
            #pragma unroll
            for (int e = 0; e < 32; e++) n2 = fmaf(tl[threadIdx.x][e], tl[threadIdx.x][e], n2);
            #pragma unroll
            for (int d = 16; d > 0; d >>= 1)
                n2 = fmaxf(n2, __shfl_xor_sync(0xffffffffu, n2, d));
            if (threadIdx.x == 0)
                atomicMax(&g_kmax2[bh], __float_as_uint(n2));
        }
    } else {
        #pragma unroll
        for (int kk = 0; kk < 2; kk++) {
            int idx = threadIdx.y*32 + threadIdx.x + kk*256;
            int e = idx >> 4, lp = idx & 15;
            float v0 = tl[2*lp][e], v1 = tl[2*lp+1][e];
            uint32_t hp = pack_bf16x2(v0, v1);
            size_t o = ((size_t)bh*32 + e)*(SEQ/2) + (l0 >> 1) + lp;
            g_vph[o] = hp;
            g_vpl[o] = pack_bf16x2(v0 - bf_low(hp), v1 - bf_high(hp));
        }
    }
}

// ================= HMMA GEMM (packed A, bf16 3-term, double-buffered) =======
#define GBM 128
#define GBN 64
#define GBK 32
#define AKP (GBK/2)
#define APAD 20

__device__ __forceinline__ float gelu_exact(float x) {
    return 0.5f * x * (1.0f + erff(x * 0.70710678118654752440f));
}

extern __shared__ uint32_t dsm[];

__global__ __launch_bounds__(256, 2)
void gemm_mma(const uint32_t* __restrict__ Ah, const uint32_t* __restrict__ Al,
              const uint32_t* __restrict__ Bh, const uint32_t* __restrict__ Bl,
              const float* __restrict__ bias, const float* __restrict__ res,
              float* __restrict__ C, uint32_t* __restrict__ Oh,
              uint32_t* __restrict__ Ol,
              int M, int N, int K, int mode) {
    uint32_t* Ash = dsm;
    uint32_t* Bsh = dsm + 2*2*GBM*APAD;

    if (mode == 0) {
        int z = blockIdx.z;
        Bh += (size_t)z * DM * (DM/2);
        Bl += (size_t)z * DM * (DM/2);
        C  += (size_t)z * (size_t)M * N;
    }
    int bm = blockIdx.y * GBM;
    int bn = blockIdx.x * GBN;
    int tid = threadIdx.x;
    int warp = tid >> 5, lane = tid & 31;
    int g = lane >> 2, j = lane & 3;
    int wm = (warp & 3) * 32;
    int wn = (warp >> 2) * 32;
    int ldkp = K >> 1;

    int arow = tid >> 3;
    int akp0 = (tid & 7) * 2;
    int bn0  = tid >> 2;
    int bkp0 = (tid & 3) * 4;

    const uint32_t* aph[4];
    const uint32_t* apl[4];
    #pragma unroll
    for (int s = 0; s < 4; s++) {
        size_t off = (size_t)(bm + arow + 32*s)*ldkp + akp0;
        aph[s] = Ah + off;
        apl[s] = Al + off;
    }
    const uint32_t* bph = Bh + (size_t)(bn + bn0)*ldkp + bkp0;
    const uint32_t* bpl = Bl + (size_t)(bn + bn0)*ldkp + bkp0;

    float acc[2][4][4];
    #pragma unroll
    for (int mt = 0; mt < 2; mt++)
        #pragma unroll
        for (int n = 0; n < 4; n++)
            #pragma unroll
            for (int r = 0; r < 4; r++) acc[mt][n][r] = 0.f;

    int nt = K / GBK;
    uint2 afh[4], afl[4]; uint4 bfh, bfl;
    #pragma unroll
    for (int s = 0; s < 4; s++) {
        afh[s] = *(const uint2*)aph[s];
        afl[s] = *(const uint2*)apl[s];
    }
    bfh = *(const uint4*)bph;
    bfl = *(const uint4*)bpl;

    {
        #pragma unroll
        for (int s = 0; s < 4; s++) {
            int row = arow + 32*s;
            uint32_t* ph = Ash + row*APAD + akp0;
            uint32_t* pl = Ash + GBM*APAD + row*APAD + akp0;
            ph[0] = afh[s].x; ph[1] = afh[s].y;
            pl[0] = afl[s].x; pl[1] = afl[s].y;
        }
        uint32_t* ph = Bsh + bn0*APAD + bkp0;
        uint32_t* pl = Bsh + GBN*APAD + bn0*APAD + bkp0;
        ph[0]=bfh.x; ph[1]=bfh.y; ph[2]=bfh.z; ph[3]=bfh.w;
        pl[0]=bfl.x; pl[1]=bfl.y; pl[2]=bfl.z; pl[3]=bfl.w;
    }
    __syncthreads();

    for (int t = 0; t < nt; t++) {
        int buf = t & 1;
        if (t + 1 < nt) {
            #pragma unroll
            for (int s = 0; s < 4; s++) {
                afh[s] = *(const uint2*)(aph[s] + (t+1)*AKP);
                afl[s] = *(const uint2*)(apl[s] + (t+1)*AKP);
            }
            bfh = *(const uint4*)(bph + (t+1)*AKP);
            bfl = *(const uint4*)(bpl + (t+1)*AKP);
        }

        const uint32_t* Ab = Ash + buf*2*GBM*APAD;
        const uint32_t* Bb = Bsh + buf*2*GBN*APAD;
        #pragma unroll
        for (int kc = 0; kc < 2; kc++) {
            uint32_t ah[2][4], al[2][4];
            #pragma unroll
            for (int mt = 0; mt < 2; mt++) {
                int r0 = wm + mt*16 + g;
                const uint32_t* pa  = Ab;
                const uint32_t* pal = Ab + GBM*APAD;
                ah[mt][0] = pa [(r0)  *APAD + kc*8 + j];
                ah[mt][1] = pa [(r0+8)*APAD + kc*8 + j];
                ah[mt][2] = pa [(r0)  *APAD + kc*8 + j + 4];
                ah[mt][3] = pa [(r0+8)*APAD + kc*8 + j + 4];
                al[mt][0] = pal[(r0)  *APAD + kc*8 + j];
                al[mt][1] = pal[(r0+8)*APAD + kc*8 + j];
                al[mt][2] = pal[(r0)  *APAD + kc*8 + j + 4];
                al[mt][3] = pal[(r0+8)*APAD + kc*8 + j + 4];
            }
            #pragma unroll
            for (int n = 0; n < 4; n++) {
                int c0 = wn + n*8 + g;
                uint32_t bh2[2], bl2[2];
                bh2[0] = Bb[c0*APAD + kc*8 + j];
                bh2[1] = Bb[c0*APAD + kc*8 + j + 4];
                bl2[0] = Bb[GBN*APAD + c0*APAD + kc*8 + j];
                bl2[1] = Bb[GBN*APAD + c0*APAD + kc*8 + j + 4];
                #pragma unroll
                for (int mt = 0; mt < 2; mt++) {
                    mma_bf16(acc[mt][n], ah[mt], bh2);
                    mma_bf16(acc[mt][n], al[mt], bh2);
                    mma_bf16(acc[mt][n], ah[mt], bl2);
                }
            }
        }

        if (t + 1 < nt) {
            int nb = buf ^ 1;
            uint32_t* An = Ash + nb*2*GBM*APAD;
            uint32_t* Bn = Bsh + nb*2*GBN*APAD;
            #pragma unroll
            for (int s = 0; s < 4; s++) {
                int row = arow + 32*s;
                uint32_t* ph = An + row*APAD + akp0;
                uint32_t* pl = An + GBM*APAD + row*APAD + akp0;
                ph[0] = afh[s].x; ph[1] = afh[s].y;
                pl[0] = afl[s].x; pl[1] = afl[s].y;
            }
            uint32_t* ph = Bn + bn0*APAD + bkp0;
            uint32_t* pl = Bn + GBN*APAD + bn0*APAD + bkp0;
            ph[0]=bfh.x; ph[1]=bfh.y; ph[2]=bfh.z; ph[3]=bfh.w;
            pl[0]=bfl.x; pl[1]=bfl.y; pl[2]=bfl.z; pl[3]=bfl.w;
        }
        __syncthreads();
    }

    // ---- epilogue ----
    float2 bb[4];
    #pragma unroll
    for (int n = 0; n < 4; n++) {
        if (mode == 2 || mode == 3)
            bb[n] = *(const float2*)(bias + bn + wn + n*8 + 2*j);
        else
            bb[n] = make_float2(0.f, 0.f);
    }
    #pragma unroll
    for (int mt = 0; mt < 2; mt++) {
        #pragma unroll
        for (int rr = 0; rr < 2; rr++) {
            int row = bm + wm + mt*16 + g + rr*8;
            #pragma unroll
            for (int n = 0; n < 4; n++) {
                int col = bn + wn + n*8 + 2*j;
                size_t off = (size_t)row*N + col;
                float c0 = acc[mt][n][2*rr], c1 = acc[mt][n][2*rr + 1];
                float2 e;
                if (mode == 1) {
                    float2 r = *(const float2*)(res + off);
                    e.x = (c0 + r.x)*0.5f; e.y = (c1 + r.y)*0.5f;
                } else if (mode == 2) {
                    e.x = gelu_exact(c0 + bb[n].x); e.y = gelu_exact(c1 + bb[n].y);
                } else if (mode == 3) {
                    float2 r = *(const float2*)(res + off);
                    e.x = (c0 + bb[n].x + r.x)*0.5f; e.y = (c1 + bb[n].y + r.y)*0.5f;
                } else {
                    e.x = c0; e.y = c1;
                }
                if (C) *(float2*)(C + off) = e;
                if (Oh) {
                    uint32_t hp = pack_bf16x2(e.x, e.y);
                    uint32_t lp = pack_bf16x2(e.x - bf_low(hp), e.y - bf_high(hp));
                    size_t po = (size_t)row*(N >> 1) + (col >> 1);
                    Oh[po] = hp; Ol[po] = lp;
                }
            }
        }
    }
}

// ================= warp-MMA flash attention (static bound, exp2 domain) =====
#define KT  32
#define NIT (SEQ/KT)

__global__ __launch_bounds__(128, 3)
void attn_mma(const float* __restrict__ gq, const float* __restrict__ gmask) {
    __shared__ __align__(16) uint32_t Ksh[2][2][16][40];
    __shared__ __align__(16) uint32_t Vsh[2][2][32][20];
    __shared__ float sMask[2][KT];   // (1-mk)*(-1e30)

    int tid  = threadIdx.x;
    int warp = tid >> 5;
    int lane = tid & 31;
    int g    = lane >> 2;
    int j    = lane & 3;
    int bh   = blockIdx.y;
    int b    = bh >> 3, h = bh & 7;
    int q0   = blockIdx.x * 128 + warp * 32;

    // Q fragments, pre-scaled by log2(e)
    uint32_t qh[2][2][4], ql[2][2][4];
    float qn2[2][2] = {};
    #pragma unroll
    for (int mt = 0; mt < 2; mt++) {
        #pragma unroll
        for (int rr = 0; rr < 2; rr++) {
            int row = q0 + mt*16 + g + rr*8;
            const float* qp = gq + ((size_t)b*SEQ + row)*DM + h*DH;
            #pragma unroll
            for (int u = 0; u < 4; u++) {
                float2 v = *(const float2*)(qp + u*8 + 2*j);
                v.x *= L2E; v.y *= L2E;
                qn2[mt][rr] = fmaf(v.x, v.x, fmaf(v.y, v.y, qn2[mt][rr]));
                uint32_t hp = pack_bf16x2(v.x, v.y);
                uint32_t lp = pack_bf16x2(v.x - bf_low(hp), v.y - bf_high(hp));
                qh[mt][u>>1][rr + 2*(u&1)] = hp;
                ql[mt][u>>1][rr + 2*(u&1)] = lp;
            }
        }
    }
    #pragma unroll
    for (int mt = 0; mt < 2; mt++)
        #pragma unroll
        for (int rr = 0; rr < 2; rr++) {
            qn2[mt][rr] += __shfl_xor_sync(0xffffffffu, qn2[mt][rr], 1);
            qn2[mt][rr] += __shfl_xor_sync(0xffffffffu, qn2[mt][rr], 2);
        }

    float kmaxn = sqrtf(__uint_as_float(g_kmax2[bh]));
    float fm[2][2], cb[2][2];
    #pragma unroll
    for (int mt = 0; mt < 2; mt++) {
        fm[mt][0] = gmask[b*SEQ + q0 + mt*16 + g];
        fm[mt][1] = gmask[b*SEQ + q0 + mt*16 + g + 8];
        #pragma unroll
        for (int rr = 0; rr < 2; rr++)
            cb[mt][rr] = (fm[mt][rr] == 0.f) ? 0.f
                       : -(sqrtf(qn2[mt][rr]) * kmaxn - 43.2808512266689f);
    }

    float lrow[2][2], ofr[2][4][4];
    #pragma unroll
    for (int mt = 0; mt < 2; mt++) {
        lrow[mt][0] = 0.f; lrow[mt][1] = 0.f;
        #pragma unroll
        for (int nd = 0; nd < 4; nd++)
            #pragma unroll
            for (int r = 0; r < 4; r++) ofr[mt][nd][r] = 0.f;
    }

    int kdp = tid >> 3;
    int kkg = (tid & 7) * 4;
    int vdm = tid >> 2;
    int vpg = (tid & 3) * 4;
    const uint32_t* kbh = g_kph + ((size_t)bh*16 + kdp)*SEQ + kkg;
    const uint32_t* kbl = g_kpl + ((size_t)bh*16 + kdp)*SEQ + kkg;
    const uint32_t* vbh = g_vph + ((size_t)bh*32 + vdm)*(SEQ/2) + vpg;
    const uint32_t* vbl = g_vpl + ((size_t)bh*32 + vdm)*(SEQ/2) + vpg;
    const float* mbase = gmask + b*SEQ + tid;

    uint4 rkh, rkl, rvh, rvl; float ml = 0.f;
    rkh = *(const uint4*)(kbh);
    rkl = *(const uint4*)(kbl);
    rvh = *(const uint4*)(vbh);
    rvl = *(const uint4*)(vbl);
    if (tid < KT) ml = *mbase;

    *(uint4*)&Ksh[0][0][kdp][kkg] = rkh;
    *(uint4*)&Ksh[0][1][kdp][kkg] = rkl;
    *(uint4*)&Vsh[0][0][vdm][vpg] = rvh;
    *(uint4*)&Vsh[0][1][vdm][vpg] = rvl;
    if (tid < KT) sMask[0][tid] = (1.0f - ml) * (-1.0e30f);
    __syncthreads();

    for (int it = 0; it < NIT; it++) {
        int bufc = it & 1;
        if (it + 1 < NIT) {
            rkh = *(const uint4*)(kbh + (it+1)*KT);
            rkl = *(const uint4*)(kbl + (it+1)*KT);
            rvh = *(const uint4*)(vbh + (it+1)*(KT/2));
            rvl = *(const uint4*)(vbl + (it+1)*(KT/2));
            if (tid < KT) ml = mbase[(it+1)*KT];
        }

        float sfr[2][4][4];
        #pragma unroll
        for (int mt = 0; mt < 2; mt++)
            #pragma unroll
            for (int n = 0; n < 4; n++)
                #pragma unroll
                for (int r = 0; r < 4; r++) sfr[mt][n][r] = 0.f;

        #pragma unroll
        for (int n = 0; n < 4; n++) {
            #pragma unroll
            for (int ks = 0; ks < 2; ks++) {
                uint32_t bhi[2], blo[2];
                bhi[0] = Ksh[bufc][0][ks*8 + j][n*8 + g];
                bhi[1] = Ksh[bufc][0][ks*8 + j + 4][n*8 + g];
                blo[0] = Ksh[bufc][1][ks*8 + j][n*8 + g];
                blo[1] = Ksh[bufc][1][ks*8 + j + 4][n*8 + g];
                #pragma unroll
                for (int mt = 0; mt < 2; mt++) {
                    mma_bf16(sfr[mt][n], qh[mt][ks], bhi);
                    mma_bf16(sfr[mt][n], ql[mt][ks], bhi);
                    mma_bf16(sfr[mt][n], qh[mt][ks], blo);
                }
            }
        }

        // ---- softmax, exp2 domain: p = ex2(fm*(s2 + mk) + cb) ----
        uint32_t phr0[2][4], phr1[2][4], plr0[2][4], plr1[2][4];
        #pragma unroll
        for (int mt = 0; mt < 2; mt++) {
            float f0 = fm[mt][0], f1 = fm[mt][1];
            float c0 = cb[mt][0], c1 = cb[mt][1];
            float ls0 = 0.f, ls1 = 0.f;
            #pragma unroll
            for (int n = 0; n < 4; n++) {
                float mk0 = sMask[bufc][n*8 + 2*j];
                float mk1 = sMask[bufc][n*8 + 2*j + 1];
                float p0 = ex2f(fmaf(f0, sfr[mt][n][0] + mk0, c0));
                float p1 = ex2f(fmaf(f0, sfr[mt][n][1] + mk1, c0));
                float p2 = ex2f(fmaf(f1, sfr[mt][n][2] + mk0, c1));
                float p3 = ex2f(fmaf(f1, sfr[mt][n][3] + mk1, c1));
                ls0 += p0 + p1; ls1 += p2 + p3;
                uint32_t h01 = pack_bf16x2(p0, p1);
                uint32_t h23 = pack_bf16x2(p2, p3);
                phr0[mt][n] = h01;
                phr1[mt][n] = h23;
                plr0[mt][n] = pack_bf16x2(p0 - bf_low(h01), p1 - bf_high(h01));
                plr1[mt][n] = pack_bf16x2(p2 - bf_low(h23), p3 - bf_high(h23));
            }
            lrow[mt][0] += ls0; lrow[mt][1] += ls1;
        }

        #pragma unroll
        for (int nd = 0; nd < 4; nd++) {
            #pragma unroll
            for (int k2 = 0; k2 < 2; k2++) {
                uint32_t bhi[2], blo[2];
                bhi[0] = Vsh[bufc][0][nd*8 + g][k2*8 + j];
                bhi[1] = Vsh[bufc][0][nd*8 + g][k2*8 + j + 4];
                blo[0] = Vsh[bufc][1][nd*8 + g][k2*8 + j];
                blo[1] = Vsh[bufc][1][nd*8 + g][k2*8 + j + 4];
                #pragma unroll
                for (int mt = 0; mt < 2; mt++) {
                    uint32_t ahi[4] = {phr0[mt][2*k2], phr1[mt][2*k2],
                                       phr0[mt][2*k2+1], phr1[mt][2*k2+1]};
                    uint32_t alo[4] = {plr0[mt][2*k2], plr1[mt][2*k2],
                                       plr0[mt][2*k2+1], plr1[mt][2*k2+1]};
                    mma_bf16(ofr[mt][nd], ahi, bhi);
                    mma_bf16(ofr[mt][nd], ahi, blo);
                    mma_bf16(ofr[mt][nd], alo, bhi);
                }
            }
        }

        if (it + 1 < NIT) {
            int bufn = bufc ^ 1;
            *(uint4*)&Ksh[bufn][0][kdp][kkg] = rkh;
            *(uint4*)&Ksh[bufn][1][kdp][kkg] = rkl;
            *(uint4*)&Vsh[bufn][0][vdm][vpg] = rvh;
            *(uint4*)&Vsh[bufn][1][vdm][vpg] = rvl;
            if (tid < KT) sMask[bufn][tid] = (1.0f - ml) * (-1.0e30f);
        }
        __syncthreads();
    }

    // ---- epilogue: emit packed bf16 hi/lo O planes directly ----
    #pragma unroll
    for (int mt = 0; mt < 2; mt++) {
        float l0 = lrow[mt][0], l1 = lrow[mt][1];
        l0 += __shfl_xor_sync(0xffffffffu, l0, 1);
        l0 += __shfl_xor_sync(0xffffffffu, l0, 2);
        l1 += __shfl_xor_sync(0xffffffffu, l1, 1);
        l1 += __shfl_xor_sync(0xffffffffu, l1, 2);
        float inv0 = 1.0f / l0, inv1 = 1.0f / l1;
        #pragma unroll
        for (int nd = 0; nd < 4; nd++) {
            int kp = h*16 + nd*4 + j;
            size_t row0 = (size_t)b*SEQ + q0 + mt*16 + g;
            float e0 = ofr[mt][nd][0]*inv0, e1 = ofr[mt][nd][1]*inv0;
            float e2 = ofr[mt][nd][2]*inv1, e3 = ofr[mt][nd][3]*inv1;
            uint32_t hp0 = pack_bf16x2(e0, e1);
            uint32_t hp1 = pack_bf16x2(e2, e3);
            g_po_h[row0*128 + kp]       = hp0;
            g_po_l[row0*128 + kp]       = pack_bf16x2(e0 - bf_low(hp0), e1 - bf_high(hp0));
            g_po_h[(row0 + 8)*128 + kp] = hp1;
            g_po_l[(row0 + 8)*128 + kp] = pack_bf16x2(e2 - bf_low(hp1), e3 - bf_high(hp1));
        }
    }
}

// ================= launch =================
extern "C" void kernel_launch(void* const* d_in, const int* in_sizes, int n_in,
                              void* d_out, int out_size) {
    const float* x    = (const float*)d_in[0];
    const float* mask = (const float*)d_in[1];
    const float* Wq   = (const float*)d_in[2];
    const float* Wk   = (const float*)d_in[3];
    const float* Wv   = (const float*)d_in[4];
    const float* Wo   = (const float*)d_in[5];
    const float* W1   = (const float*)d_in[6];
    const float* b1   = (const float*)d_in[7];
    const float* W2   = (const float*)d_in[8];
    const float* b2   = (const float*)d_in[9];
    float* out = (float*)d_out;

    float *qkv_p, *xc_p;
    uint32_t *pxch, *pxcl, *pffh, *pffl, *poh, *pol;
    uint32_t *pqkh, *pqkl, *pwoh, *pwol, *pw1h, *pw1l, *pw2h, *pw2l;
    cudaGetSymbolAddress((void**)&qkv_p, g_qkv);
    cudaGetSymbolAddress((void**)&xc_p,  g_xc);
    cudaGetSymbolAddress((void**)&pxch,  g_pxc_h);
    cudaGetSymbolAddress((void**)&pxcl,  g_pxc_l);
    cudaGetSymbolAddress((void**)&pffh,  g_pff_h);
    cudaGetSymbolAddress((void**)&pffl,  g_pff_l);
    cudaGetSymbolAddress((void**)&poh,   g_po_h);
    cudaGetSymbolAddress((void**)&pol,   g_po_l);
    cudaGetSymbolAddress((void**)&pqkh,  g_pwqkv_h);
    cudaGetSymbolAddress((void**)&pqkl,  g_pwqkv_l);
    cudaGetSymbolAddress((void**)&pwoh,  g_pwo_h);
    cudaGetSymbolAddress((void**)&pwol,  g_pwo_l);
    cudaGetSymbolAddress((void**)&pw1h,  g_pw1_h);
    cudaGetSymbolAddress((void**)&pw1l,  g_pw1_l);
    cudaGetSymbolAddress((void**)&pw2h,  g_pw2_h);
    cudaGetSymbolAddress((void**)&pw2l,  g_pw2_l);

    const int SMEM_GEMM = (2*2*GBM*APAD + 2*2*GBN*APAD) * 4;
    cudaFuncSetAttribute(gemm_mma, cudaFuncAttributeMaxDynamicSharedMemorySize, SMEM_GEMM);

    pack_qkv<<<(NL*3*DM*(DM/2) + 255)/256, 256>>>(Wq, Wk, Wv);
    pack_w<<<(NL*DM*(DM/2) + 255)/256, 256>>>(Wo, pwoh, pwol, DM, DM);
    pack_w<<<(NL*DF*(DM/2) + 255)/256, 256>>>(W1, pw1h, pw1l, DM, DF);
    pack_w<<<(NL*DM*(DF/2) + 255)/256, 256>>>(W2, pw2h, pw2l, DF, DM);
    pack_a<<<(MR*128 + 255)/256, 256>>>(x, pxch, pxcl, MR*128);

    const size_t QKV_STRIDE = (size_t)MR * DM;

    for (int n = 0; n < NL; n++) {
        const float* xin = (n == 0) ? x : xc_p;

        // QKV (A = packed xc)
        gemm_mma<<<dim3(DM/GBN, MR/GBM, 3), 256, SMEM_GEMM>>>(
            pxch, pxcl,
            pqkh + (size_t)n*3*DM*(DM/2), pqkl + (size_t)n*3*DM*(DM/2),
            nullptr, nullptr, qkv_p, nullptr, nullptr, MR, DM, DM, 0);

        reset_kmax<<<1, 32>>>();
        pack_kv<<<dim3(SEQ/32, NB*NH, 2), dim3(32, 8)>>>(
            qkv_p + QKV_STRIDE, qkv_p + 2*QKV_STRIDE);

        attn_mma<<<dim3(SEQ/128, NB*NH), 128>>>(qkv_p, mask);

        // xc = (o @ Wo + xin)*0.5   (A = packed o; emits packed xc)
        gemm_mma<<<dim3(DM/GBN, MR/GBM, 1), 256, SMEM_GEMM>>>(
            poh, pol,
            pwoh + (size_t)n*DM*(DM/2), pwol + (size_t)n*DM*(DM/2),
            nullptr, xin, xc_p, pxch, pxcl, MR, DM, DM, 1);

        // ff = gelu(xc @ W1 + b1)   (A = packed xc; emits packed ff, no fp32)
        gemm_mma<<<dim3(DF/GBN, MR/GBM, 1), 256, SMEM_GEMM>>>(
            pxch, pxcl,
            pw1h + (size_t)n*DF*(DM/2), pw1l + (size_t)n*DF*(DM/2),
            b1 + (size_t)n*DF, nullptr, nullptr, pffh, pffl, MR, DF, DM, 2);

        // xc = (ff @ W2 + b2 + xc)*0.5   (A = packed ff; emits packed xc)
        float* dst = (n == NL - 1) ? out : xc_p;
        uint32_t* oh = (n == NL - 1) ? nullptr : pxch;
        uint32_t* ol = (n == NL - 1) ? nullptr : pxcl;
        gemm_mma<<<dim3(DM/GBN, MR/GBM, 1), 256, SMEM_GEMM>>>(
            pffh, pffl,
            pw2h + (size_t)n*DM*(DF/2), pw2l + (size_t)n*DM*(DF/2),
            b2 + (size_t)n*DM, xc_p, dst, oh, ol, MR, DM, DF, 3);
    }
}